// round 5
// baseline (speedup 1.0000x reference)
#include <cuda_runtime.h>
#include <math.h>

#define SIMS 64
#define SD 65536            // 2^16 state dim
#define TILES 16            // 16 tiles of 4096 amps per sim (qubits 0..11 local)
#define PI_F 3.14159265358979323846f
#define INV_SQRT2 0.70710678118654752440f

// ---------------- device scratch (static, no allocation) ----------------
__device__ __align__(16) float2 g_state[SIMS * SD];   // 32 MB
__device__ __align__(16) float2 g_d0[SD];             // CRZ layer-0 phase table
__device__ __align__(16) float2 g_d1[SD];             // CRZ layer-1 phase table
__device__ float g_TL[SIMS][256];                     // product tables (qubits 0..7)
__device__ float g_TH[SIMS][256];                     // product tables (qubits 8..15)
__device__ float g_cA[SIMS][16], g_sA[SIMS][16];      // cos/sin((w_ry0+enc)/2)
__device__ float g_cB[16], g_sB[16];                  // cos/sin(w_ry1/2)
__device__ float g_partial[SIMS][TILES][16];          // per-tile Z partials

// ---------------- precompute: per-sim encoding params ----------------
__global__ void k_sim(const float* __restrict__ x,
                      const float* __restrict__ wry,
                      const float* __restrict__ scale) {
    const int sim = blockIdx.x;        // 64 blocks
    const int t = threadIdx.x;         // 256 threads
    __shared__ float v0[16], v1[16];
    if (t < 16) {
        const int q = t;
        const int bb = sim >> 3, p = sim & 7;
        // inputs[sim][q] = x[bb, (q/4)*32 + p*4 + (q%4)]
        const float xv = x[bb * 128 + (q >> 2) * 32 + p * 4 + (q & 3)];
        const float enc = tanhf(xv * scale[0]) * PI_F;
        float se, ce;
        sincosf(enc * 0.5f, &se, &ce);
        v0[q] = (ce - se) * INV_SQRT2;   // RY(enc)*H|0> amplitude for bit 0
        v1[q] = (ce + se) * INV_SQRT2;   // bit 1
        float sA, cA;
        sincosf((wry[q] + enc) * 0.5f, &sA, &cA);   // merged RY(w_ry0 + enc)
        g_cA[sim][q] = cA;  g_sA[sim][q] = sA;
        if (sim == 0) {
            float sB, cB;
            sincosf(wry[16 + q] * 0.5f, &sB, &cB);
            g_cB[q] = cB;  g_sB[q] = sB;
        }
    }
    __syncthreads();
    // product tables: one entry per thread
    const int m = t;
    float pl = 1.0f, ph = 1.0f;
#pragma unroll
    for (int q = 0; q < 8; q++) {
        pl *= ((m >> q) & 1) ? v1[q] : v0[q];
        ph *= ((m >> q) & 1) ? v1[8 + q] : v0[8 + q];
    }
    g_TL[sim][m] = pl;
    g_TH[sim][m] = ph;
}

// ---------------- precompute: CRZ diagonal phase tables ----------------
__global__ void k_tab(const float* __restrict__ wcrz) {
    __shared__ float w[32];
    if (threadIdx.x < 32) w[threadIdx.x] = 0.5f * wcrz[threadIdx.x];
    __syncthreads();
    const int b = blockIdx.x * blockDim.x + threadIdx.x;  // 65536 threads
    float a0 = 0.0f, a1 = 0.0f;
#pragma unroll
    for (int q = 0; q < 16; q++) {
        if ((b >> q) & 1) {  // control bit set
            const int t1 = (q + 1) & 15;   // layer 0, shift 1
            const int t2 = (q + 2) & 15;   // layer 1, shift 2
            a0 += ((b >> t1) & 1) ? w[q] : -w[q];
            a1 += ((b >> t2) & 1) ? w[16 + q] : -w[16 + q];
        }
    }
    float s0, c0, s1, c1;
    sincosf(a0, &s0, &c0);
    sincosf(a1, &s1, &c1);
    g_d0[b] = make_float2(c0, s0);
    g_d1[b] = make_float2(c1, s1);
}

// ---------------- butterfly sweep over qubits 0..11 within a 4096-amp tile ----------------
// Layout: thread t (0..255) holds local amps l = (j<<8)|t for j=0..15.
//   qubits 8..11 -> j bits (registers), qubits 0..4 -> lane bits (shfl),
//   qubits 5..7  -> warp-id bits (smem exchange).
__device__ __forceinline__ void sweep_low(float2 a[16], const float* sc, const float* ss,
                                          float2* sbuf, int t, int lane) {
    // qubits 8..11 (intra-thread)
#pragma unroll
    for (int q = 0; q < 4; q++) {
        const float c = sc[8 + q], s = ss[8 + q];
#pragma unroll
        for (int p = 0; p < 8; p++) {
            const int j0 = ((p >> q) << (q + 1)) | (p & ((1 << q) - 1));
            const int j1 = j0 | (1 << q);
            const float r0 = c * a[j0].x - s * a[j1].x;
            const float r1 = s * a[j0].x + c * a[j1].x;
            const float i0 = c * a[j0].y - s * a[j1].y;
            const float i1 = s * a[j0].y + c * a[j1].y;
            a[j0].x = r0; a[j1].x = r1; a[j0].y = i0; a[j1].y = i1;
        }
    }
    // qubits 0..4 (lane bits via shuffle)
#pragma unroll
    for (int q = 0; q < 5; q++) {
        const float c = sc[q], s = ss[q];
        const int m = 1 << q;
        const float sgn = (lane & m) ? s : -s;
#pragma unroll
        for (int j = 0; j < 16; j++) {
            const float ox = __shfl_xor_sync(0xffffffffu, a[j].x, m);
            const float oy = __shfl_xor_sync(0xffffffffu, a[j].y, m);
            a[j].x = fmaf(sgn, ox, c * a[j].x);
            a[j].y = fmaf(sgn, oy, c * a[j].y);
        }
    }
    // qubits 5..7 (cross-warp via smem)
#pragma unroll
    for (int q = 5; q < 8; q++) {
        const float c = sc[q], s = ss[q];
        const int m = 1 << q;
        __syncthreads();
#pragma unroll
        for (int j = 0; j < 16; j++) sbuf[(j << 8) | t] = a[j];
        __syncthreads();
        const int pt = t ^ m;
        const float sgn = (t & m) ? s : -s;
#pragma unroll
        for (int j = 0; j < 16; j++) {
            const float2 o = sbuf[(j << 8) | pt];
            a[j].x = fmaf(sgn, o.x, c * a[j].x);
            a[j].y = fmaf(sgn, o.y, c * a[j].y);
        }
    }
}

// ---------------- K1: init * D0, then RY(w0+enc) on qubits 0..11 ----------------
__global__ void __launch_bounds__(256) k_pass1() {
    const int sim = blockIdx.x >> 4;
    const int tile = blockIdx.x & 15;
    const int t = threadIdx.x;
    const int lane = t & 31;
    __shared__ float2 sbuf[4096];
    __shared__ float sc[16], ss[16], sTH[16];
    if (t < 16) {
        sc[t] = g_cA[sim][t];
        ss[t] = g_sA[sim][t];
        sTH[t] = g_TH[sim][(tile << 4) | t];
    }
    __syncthreads();
    const float tl = g_TL[sim][t];
    const int gb = tile << 12;
    float2 a[16];
#pragma unroll
    for (int j = 0; j < 16; j++) {
        const int b = gb | (j << 8) | t;
        const float amp = tl * sTH[j];
        const float2 d = g_d0[b];
        a[j] = make_float2(amp * d.x, amp * d.y);
    }
    sweep_low(a, sc, ss, sbuf, t, lane);
    float2* st = g_state + sim * SD + gb;
#pragma unroll
    for (int j = 0; j < 16; j++) st[(j << 8) | t] = a[j];
}

// ---------------- K2: RY(w0+enc) qubits 12..15, then D1, then RY(w1) qubits 12..15 ----------------
__device__ __forceinline__ void bf4(float4& a0, float4& a1, float c, float s) {
    const float nx0 = c * a0.x - s * a1.x;  const float nx1 = s * a0.x + c * a1.x;
    const float ny0 = c * a0.y - s * a1.y;  const float ny1 = s * a0.y + c * a1.y;
    const float nz0 = c * a0.z - s * a1.z;  const float nz1 = s * a0.z + c * a1.z;
    const float nw0 = c * a0.w - s * a1.w;  const float nw1 = s * a0.w + c * a1.w;
    a0 = make_float4(nx0, ny0, nz0, nw0);
    a1 = make_float4(nx1, ny1, nz1, nw1);
}

__global__ void __launch_bounds__(256) k_high() {
    const int sim = blockIdx.x >> 3;
    const int blk = blockIdx.x & 7;
    const int t = threadIdx.x;
    const int low0 = (blk << 9) | (t << 1);   // 2 consecutive low offsets per thread
    float cA[4], sA[4], cB[4], sB[4];
#pragma unroll
    for (int q = 0; q < 4; q++) {
        cA[q] = g_cA[sim][12 + q];  sA[q] = g_sA[sim][12 + q];
        cB[q] = g_cB[12 + q];       sB[q] = g_sB[12 + q];
    }
    float4* st = reinterpret_cast<float4*>(g_state + sim * SD);
    float4 a[16];
#pragma unroll
    for (int k = 0; k < 16; k++) a[k] = st[(k << 11) | (low0 >> 1)];
    // RY(w0+enc) high qubits
#pragma unroll
    for (int q = 0; q < 4; q++) {
#pragma unroll
        for (int p = 0; p < 8; p++) {
            const int k0 = ((p >> q) << (q + 1)) | (p & ((1 << q) - 1));
            const int k1 = k0 | (1 << q);
            bf4(a[k0], a[k1], cA[q], sA[q]);
        }
    }
    // D1 pointwise phase
#pragma unroll
    for (int k = 0; k < 16; k++) {
        const int b = (k << 12) | low0;
        const float4 d = *reinterpret_cast<const float4*>(&g_d1[b]);  // (c0,s0,c1,s1)
        const float nx = a[k].x * d.x - a[k].y * d.y;
        const float ny = a[k].x * d.y + a[k].y * d.x;
        const float nz = a[k].z * d.z - a[k].w * d.w;
        const float nw = a[k].z * d.w + a[k].w * d.z;
        a[k] = make_float4(nx, ny, nz, nw);
    }
    // RY(w1) high qubits
#pragma unroll
    for (int q = 0; q < 4; q++) {
#pragma unroll
        for (int p = 0; p < 8; p++) {
            const int k0 = ((p >> q) << (q + 1)) | (p & ((1 << q) - 1));
            const int k1 = k0 | (1 << q);
            bf4(a[k0], a[k1], cB[q], sB[q]);
        }
    }
#pragma unroll
    for (int k = 0; k < 16; k++) st[(k << 11) | (low0 >> 1)] = a[k];
}

// ---------------- K3: RY(w1) qubits 0..11 + measurement partials ----------------
__global__ void __launch_bounds__(256) k_pass3() {
    const int sim = blockIdx.x >> 4;
    const int tile = blockIdx.x & 15;
    const int t = threadIdx.x;
    const int lane = t & 31;
    __shared__ float2 sbuf[4096];
    __shared__ float sc[16], ss[16];
    __shared__ float wred[8][16];
    if (t < 16) { sc[t] = g_cB[t]; ss[t] = g_sB[t]; }
    __syncthreads();
    const float2* st = g_state + sim * SD + (tile << 12);
    float2 a[16];
#pragma unroll
    for (int j = 0; j < 16; j++) a[j] = st[(j << 8) | t];
    sweep_low(a, sc, ss, sbuf, t, lane);

    // measurement: probs + Z expectations
    float ptot = 0.0f, z8 = 0.0f, z9 = 0.0f, z10 = 0.0f, z11 = 0.0f;
#pragma unroll
    for (int j = 0; j < 16; j++) {
        const float p = a[j].x * a[j].x + a[j].y * a[j].y;
        ptot += p;
        z8  += (j & 1) ? -p : p;
        z9  += (j & 2) ? -p : p;
        z10 += (j & 4) ? -p : p;
        z11 += (j & 8) ? -p : p;
    }
    float v[13];
#pragma unroll
    for (int q = 0; q < 8; q++) v[q] = ((t >> q) & 1) ? -ptot : ptot;  // qubits 0..7: sign by t bits
    v[8] = z8; v[9] = z9; v[10] = z10; v[11] = z11; v[12] = ptot;
#pragma unroll
    for (int k = 0; k < 13; k++) {
        float xv = v[k];
#pragma unroll
        for (int o = 16; o > 0; o >>= 1) xv += __shfl_xor_sync(0xffffffffu, xv, o);
        v[k] = xv;
    }
    const int w = t >> 5;
    if (lane == 0) {
#pragma unroll
        for (int k = 0; k < 13; k++) wred[w][k] = v[k];
    }
    __syncthreads();
    if (t < 13) {
        float s = 0.0f;
#pragma unroll
        for (int w2 = 0; w2 < 8; w2++) s += wred[w2][t];
        if (t < 12) {
            g_partial[sim][tile][t] = s;
        } else {  // t == 12: total prob -> qubits 12..15 (sign fixed per tile)
#pragma unroll
            for (int q = 12; q < 16; q++) {
                const float sg = ((tile >> (q - 12)) & 1) ? -1.0f : 1.0f;
                g_partial[sim][tile][q] = sg * s;
            }
        }
    }
}

// ---------------- K4: deterministic reduce, clip, permute to output ----------------
__global__ void k_out(float* __restrict__ out) {
    const int i = threadIdx.x;   // 1024 = 64 sims * 16 qubits
    const int sim = i >> 4, q = i & 15;
    float s = 0.0f;
#pragma unroll
    for (int tl = 0; tl < 16; tl++) s += g_partial[sim][tl][q];
    s = fminf(1.0f, fmaxf(-1.0f, s));
    const int bb = sim >> 3, p = sim & 7, h = q >> 2, w = q & 3;
    out[bb * 128 + h * 32 + p * 4 + w] = s;
}

// ---------------- launch ----------------
extern "C" void kernel_launch(void* const* d_in, const int* in_sizes, int n_in,
                              void* d_out, int out_size) {
    const float* x     = (const float*)d_in[0];
    const float* wcrz  = (const float*)d_in[1];
    const float* wry   = (const float*)d_in[2];
    const float* scale = (const float*)d_in[3];
    float* out = (float*)d_out;

    k_sim<<<SIMS, 256>>>(x, wry, scale);
    k_tab<<<256, 256>>>(wcrz);
    k_pass1<<<SIMS * TILES, 256>>>();
    k_high<<<SIMS * 8, 256>>>();
    k_pass3<<<SIMS * TILES, 256>>>();
    k_out<<<1, 1024>>>(out);
}

// round 8
// speedup vs baseline: 1.1862x; 1.1862x over previous
#include <cuda_runtime.h>
#include <math.h>

#define SIMS 64
#define SD 65536            // 2^16 state dim
#define PI_F 3.14159265358979323846f
#define INV_SQRT2 0.70710678118654752440f

// ---------------- device scratch (static, no allocation) ----------------
__device__ __align__(16) float2 g_state[SIMS * SD];   // 32 MB (L2-resident)
__device__ float2 g_A0[512];    // CRZ layer0, controls q0..7  (idx bits 0..8 = qubit bits 0..8)
__device__ float2 g_B0[512];    // CRZ layer0, controls q8..15 (idx bits 0..7 = q8..15, bit 8 = q0)
__device__ float2 g_A1[1024];   // CRZ layer1, controls q0..7  (idx bits 0..9 = qubit bits 0..9)
__device__ float2 g_B1[1024];   // CRZ layer1, controls q8..15 (idx bits 0..7 = q8..15, bits 8..9 = q0..1)
__device__ float g_TL[SIMS][256];                     // product tables (qubits 0..7)
__device__ float g_TH[SIMS][256];                     // product tables (qubits 8..15)
__device__ float g_cA[SIMS][16], g_sA[SIMS][16];      // cos/sin((w_ry0+enc)/2)
__device__ float g_cB[16], g_sB[16];                  // cos/sin(w_ry1/2)
__device__ float g_partial[SIMS][16][16];             // per-tile Z partials

// ---------------- prep: per-sim params + split CRZ phase tables ----------------
__global__ void k_prep(const float* __restrict__ x,
                       const float* __restrict__ wcrz,
                       const float* __restrict__ wry,
                       const float* __restrict__ scale) {
    const int blk = blockIdx.x;
    const int t = threadIdx.x;         // 256 threads
    if (blk < SIMS) {
        const int sim = blk;
        __shared__ float v0[16], v1[16];
        if (t < 16) {
            const int q = t;
            const int bb = sim >> 3, p = sim & 7;
            const float xv = x[bb * 128 + (q >> 2) * 32 + p * 4 + (q & 3)];
            const float enc = tanhf(xv * scale[0]) * PI_F;
            float se, ce;
            sincosf(enc * 0.5f, &se, &ce);
            v0[q] = (ce - se) * INV_SQRT2;
            v1[q] = (ce + se) * INV_SQRT2;
            float sA, cA;
            sincosf((wry[q] + enc) * 0.5f, &sA, &cA);   // merged RY(w_ry0 + enc)
            g_cA[sim][q] = cA;  g_sA[sim][q] = sA;
            if (sim == 0) {
                float sB, cB;
                sincosf(wry[16 + q] * 0.5f, &sB, &cB);
                g_cB[q] = cB;  g_sB[q] = sB;
            }
        }
        __syncthreads();
        const int m = t;
        float pl = 1.0f, ph = 1.0f;
#pragma unroll
        for (int q = 0; q < 8; q++) {
            pl *= ((m >> q) & 1) ? v1[q] : v0[q];
            ph *= ((m >> q) & 1) ? v1[8 + q] : v0[8 + q];
        }
        g_TL[sim][m] = pl;
        g_TH[sim][m] = ph;
    } else {
        // table builder blocks: blk = 64..67
        __shared__ float w[32];
        if (t < 32) w[t] = 0.5f * wcrz[t];
        __syncthreads();
        const int which = blk - SIMS;
        if (which == 0) {          // A0: controls q0..7, targets q+1 (bits 1..8)
            for (int i = t; i < 512; i += 256) {
                float a = 0.0f;
#pragma unroll
                for (int q = 0; q < 8; q++)
                    if ((i >> q) & 1) a += ((i >> (q + 1)) & 1) ? w[q] : -w[q];
                float s, c; sincosf(a, &s, &c);
                g_A0[i] = make_float2(c, s);
            }
        } else if (which == 1) {   // B0: controls q8..15, targets q+1 mod 16
            for (int i = t; i < 512; i += 256) {
                float a = 0.0f;
#pragma unroll
                for (int q = 8; q < 16; q++) {
                    if ((i >> (q - 8)) & 1) {
                        const int tq = (q + 1) & 15;
                        const int tb = (tq == 0) ? ((i >> 8) & 1) : ((i >> (tq - 8)) & 1);
                        a += tb ? w[q] : -w[q];
                    }
                }
                float s, c; sincosf(a, &s, &c);
                g_B0[i] = make_float2(c, s);
            }
        } else if (which == 2) {   // A1: controls q0..7, targets q+2 (bits 2..9)
            for (int i = t; i < 1024; i += 256) {
                float a = 0.0f;
#pragma unroll
                for (int q = 0; q < 8; q++)
                    if ((i >> q) & 1) a += ((i >> (q + 2)) & 1) ? w[16 + q] : -w[16 + q];
                float s, c; sincosf(a, &s, &c);
                g_A1[i] = make_float2(c, s);
            }
        } else {                   // B1: controls q8..15, targets q+2 mod 16
            for (int i = t; i < 1024; i += 256) {
                float a = 0.0f;
#pragma unroll
                for (int q = 8; q < 16; q++) {
                    if ((i >> (q - 8)) & 1) {
                        const int tq = (q + 2) & 15;
                        const int tb = (tq >= 8) ? ((i >> (tq - 8)) & 1) : ((i >> (8 + tq)) & 1);
                        a += tb ? w[16 + q] : -w[16 + q];
                    }
                }
                float s, c; sincosf(a, &s, &c);
                g_B1[i] = make_float2(c, s);
            }
        }
    }
}

// ---------------- butterfly helpers ----------------
// RY butterfly on register-index bit qb of a 16-entry array.
__device__ __forceinline__ void bf_regs(float2 a[16], int qb, float c, float s) {
#pragma unroll
    for (int p = 0; p < 8; p++) {
        const int j0 = ((p >> qb) << (qb + 1)) | (p & ((1 << qb) - 1));
        const int j1 = j0 | (1 << qb);
        const float r0 = c * a[j0].x - s * a[j1].x;
        const float r1 = s * a[j0].x + c * a[j1].x;
        const float i0 = c * a[j0].y - s * a[j1].y;
        const float i1 = s * a[j0].y + c * a[j1].y;
        a[j0].x = r0; a[j1].x = r1; a[j0].y = i0; a[j1].y = i1;
    }
}

// RY butterflies on lane bits 0..4 via warp shuffle.
__device__ __forceinline__ void bf_shfl(float2 a[16], const float* sc, const float* ss, int lane) {
#pragma unroll
    for (int q = 0; q < 5; q++) {
        const float c = sc[q], s = ss[q];
        const int m = 1 << q;
        const float sgn = (lane & m) ? s : -s;
#pragma unroll
        for (int j = 0; j < 16; j++) {
            const float ox = __shfl_xor_sync(0xffffffffu, a[j].x, m);
            const float oy = __shfl_xor_sync(0xffffffffu, a[j].y, m);
            a[j].x = fmaf(sgn, ox, c * a[j].x);
            a[j].y = fmaf(sgn, oy, c * a[j].y);
        }
    }
}

// ---------------- K1: init * D0 (split tables), RY_A on qubits 0..11, one transpose ----------------
// Layout L1: t bits 0..7 <-> qubits 0..7 (lane=0..4, warp=5..7), regs j <-> qubits 8..11.
// Layout L1': lane <-> 0..4, warp w <-> 8..10, regs jp: bits0..2 <-> 5..7, bit3 <-> 11.
__global__ void __launch_bounds__(256) k_pass1() {
    const int sim = blockIdx.x >> 4;
    const int tile = blockIdx.x & 15;
    const int t = threadIdx.x;
    const int lane = t & 31;
    const int w = t >> 5;
    __shared__ float2 sbuf[4096];
    __shared__ float sc[16], ss[16], sTH[16];
    __shared__ float2 sB0[2][16];
    if (t < 16) {
        sc[t] = g_cA[sim][t];
        ss[t] = g_sA[sim][t];
        sTH[t] = g_TH[sim][(tile << 4) | t];
    }
    if (t < 32) {
        const int b0 = t >> 4, j = t & 15;
        sB0[b0][j] = g_B0[(tile << 4) | j | (b0 << 8)];
    }
    __syncthreads();
    const float tl = g_TL[sim][t];
    const float2 pa0 = g_A0[t];
    const float2 pa1 = g_A0[t | 256];
    const int myb0 = t & 1;
    float2 a[16];
#pragma unroll
    for (int j = 0; j < 16; j++) {
        const float2 pa = (j & 1) ? pa1 : pa0;       // A0 bit8 = qubit8 = j bit0
        const float2 pb = sB0[myb0][j];
        const float cr = pa.x * pb.x - pa.y * pb.y;  // e^{i(A0+B0)}
        const float ci = pa.x * pb.y + pa.y * pb.x;
        const float amp = tl * sTH[j];
        a[j] = make_float2(amp * cr, amp * ci);
    }
    // RY_A qubits 8..11 (reg bits), 0..4 (shfl)
#pragma unroll
    for (int qb = 0; qb < 4; qb++) bf_regs(a, qb, sc[8 + qb], ss[8 + qb]);
    bf_shfl(a, sc, ss, lane);
    // transpose L1 -> L1'
#pragma unroll
    for (int j = 0; j < 16; j++) sbuf[(j << 8) | t] = a[j];
    __syncthreads();
    float2 b[16];
#pragma unroll
    for (int jp = 0; jp < 16; jp++) {
        const int oj = w | (jp & 8);     // old j = q8..10 (new w) | q11 (jp bit3)
        const int ow = jp & 7;           // old warp = q5..7
        b[jp] = sbuf[(oj << 8) | (ow << 5) | lane];
    }
    // RY_A qubits 5..7 (jp bits 0..2)
#pragma unroll
    for (int qb = 0; qb < 3; qb++) bf_regs(b, qb, sc[5 + qb], ss[5 + qb]);
    // store to canonical global addresses
    float2* st = g_state + sim * SD + (tile << 12);
#pragma unroll
    for (int jp = 0; jp < 16; jp++)
        st[lane | ((jp & 7) << 5) | (w << 8) | ((jp & 8) << 8)] = b[jp];
}

// ---------------- K2: RY_A(12..15), D1 (split tables), RY_B(12..15) ----------------
// One complex per k-slot: 32 data regs -> high occupancy. low12 = (blk<<8)|t.
__global__ void __launch_bounds__(256) k_pass2() {
    const int sim = blockIdx.x >> 4;
    const int blk = blockIdx.x & 15;
    const int t = threadIdx.x;
    const int low12 = (blk << 8) | t;
    __shared__ float2 sB1[64];           // [k][q0..1]
    __shared__ float scA[4], ssA[4], scB[4], ssB[4];
    if (t < 64) {
        const int k = t >> 2, c2 = t & 3;
        sB1[t] = g_B1[blk | (k << 4) | (c2 << 8)];
    }
    if (t < 4) {
        scA[t] = g_cA[sim][12 + t]; ssA[t] = g_sA[sim][12 + t];
        scB[t] = g_cB[12 + t];      ssB[t] = g_sB[12 + t];
    }
    __syncthreads();
    const float2 pa = g_A1[low12 & 1023];
    float2* st = g_state + sim * SD;
    float2 a[16];
#pragma unroll
    for (int k = 0; k < 16; k++) a[k] = st[(k << 12) | low12];
    // RY_A qubits 12..15 (k bits)
#pragma unroll
    for (int qb = 0; qb < 4; qb++) bf_regs(a, qb, scA[qb], ssA[qb]);
    // D1 phase: e^{iA1} * e^{iB1[k]}
    const int c2 = t & 3;
#pragma unroll
    for (int k = 0; k < 16; k++) {
        const float2 pb = sB1[(k << 2) | c2];
        const float cr = pa.x * pb.x - pa.y * pb.y;
        const float ci = pa.x * pb.y + pa.y * pb.x;
        const float nx = a[k].x * cr - a[k].y * ci;
        const float ny = a[k].x * ci + a[k].y * cr;
        a[k] = make_float2(nx, ny);
    }
    // RY_B qubits 12..15
#pragma unroll
    for (int qb = 0; qb < 4; qb++) bf_regs(a, qb, scB[qb], ssB[qb]);
#pragma unroll
    for (int k = 0; k < 16; k++) st[(k << 12) | low12] = a[k];
}

// ---------------- K3: RY_B qubits 0..11 (load in L1', one transpose back) + measurement ----------------
__global__ void __launch_bounds__(256) k_pass3() {
    const int sim = blockIdx.x >> 4;
    const int tile = blockIdx.x & 15;
    const int t = threadIdx.x;
    const int lane = t & 31;
    const int w = t >> 5;
    __shared__ float2 sbuf[4096];
    __shared__ float sc[16], ss[16];
    __shared__ float wred[8][16];
    if (t < 16) { sc[t] = g_cB[t]; ss[t] = g_sB[t]; }
    __syncthreads();
    // load in layout L1' (lane<->0..4, w<->8..10, jp bits0..2<->5..7, bit3<->11)
    const float2* stg = g_state + sim * SD + (tile << 12);
    float2 b[16];
#pragma unroll
    for (int jp = 0; jp < 16; jp++)
        b[jp] = stg[lane | ((jp & 7) << 5) | (w << 8) | ((jp & 8) << 8)];
    // RY_B qubits 5..7 (jp bits 0..2) and 11 (jp bit 3)
#pragma unroll
    for (int qb = 0; qb < 3; qb++) bf_regs(b, qb, sc[5 + qb], ss[5 + qb]);
    bf_regs(b, 3, sc[11], ss[11]);
    // RY_B qubits 0..4 (shfl)
    bf_shfl(b, sc, ss, lane);
    // transpose L1' -> L1
#pragma unroll
    for (int jp = 0; jp < 16; jp++)
        sbuf[lane | ((jp & 7) << 5) | (w << 8) | ((jp & 8) << 8)] = b[jp];
    __syncthreads();
    float2 a[16];
#pragma unroll
    for (int j = 0; j < 16; j++) a[j] = sbuf[(j << 8) | t];
    // RY_B qubits 8..10 (j bits 0..2; q11 already done)
#pragma unroll
    for (int qb = 0; qb < 3; qb++) bf_regs(a, qb, sc[8 + qb], ss[8 + qb]);

    // measurement: probs + Z expectations (layout L1: t<->q0..7, j<->q8..11, tile<->q12..15)
    float ptot = 0.0f, z8 = 0.0f, z9 = 0.0f, z10 = 0.0f, z11 = 0.0f;
#pragma unroll
    for (int j = 0; j < 16; j++) {
        const float p = a[j].x * a[j].x + a[j].y * a[j].y;
        ptot += p;
        z8  += (j & 1) ? -p : p;
        z9  += (j & 2) ? -p : p;
        z10 += (j & 4) ? -p : p;
        z11 += (j & 8) ? -p : p;
    }
    float v[13];
#pragma unroll
    for (int q = 0; q < 8; q++) v[q] = ((t >> q) & 1) ? -ptot : ptot;
    v[8] = z8; v[9] = z9; v[10] = z10; v[11] = z11; v[12] = ptot;
#pragma unroll
    for (int k = 0; k < 13; k++) {
        float xv = v[k];
#pragma unroll
        for (int o = 16; o > 0; o >>= 1) xv += __shfl_xor_sync(0xffffffffu, xv, o);
        v[k] = xv;
    }
    if (lane == 0) {
#pragma unroll
        for (int k = 0; k < 13; k++) wred[w][k] = v[k];
    }
    __syncthreads();
    if (t < 13) {
        float s = 0.0f;
#pragma unroll
        for (int w2 = 0; w2 < 8; w2++) s += wred[w2][t];
        if (t < 12) {
            g_partial[sim][tile][t] = s;
        } else {
#pragma unroll
            for (int q = 12; q < 16; q++) {
                const float sg = ((tile >> (q - 12)) & 1) ? -1.0f : 1.0f;
                g_partial[sim][tile][q] = sg * s;
            }
        }
    }
}

// ---------------- K4: deterministic reduce, clip, permute to output ----------------
__global__ void k_out(float* __restrict__ out) {
    const int i = threadIdx.x;   // 1024 = 64 sims * 16 qubits
    const int sim = i >> 4, q = i & 15;
    float s = 0.0f;
#pragma unroll
    for (int tl = 0; tl < 16; tl++) s += g_partial[sim][tl][q];
    s = fminf(1.0f, fmaxf(-1.0f, s));
    const int bb = sim >> 3, p = sim & 7, h = q >> 2, ww = q & 3;
    out[bb * 128 + h * 32 + p * 4 + ww] = s;
}

// ---------------- launch ----------------
extern "C" void kernel_launch(void* const* d_in, const int* in_sizes, int n_in,
                              void* d_out, int out_size) {
    const float* x     = (const float*)d_in[0];
    const float* wcrz  = (const float*)d_in[1];
    const float* wry   = (const float*)d_in[2];
    const float* scale = (const float*)d_in[3];
    float* out = (float*)d_out;

    k_prep<<<SIMS + 4, 256>>>(x, wcrz, wry, scale);
    k_pass1<<<SIMS * 16, 256>>>();
    k_pass2<<<SIMS * 16, 256>>>();
    k_pass3<<<SIMS * 16, 256>>>();
    k_out<<<1, 1024>>>(out);
}